// round 1
// baseline (speedup 1.0000x reference)
#include <cuda_runtime.h>

// 2x trilinear upsample (TF1 legacy mapping, scale=0.5) of (4,32,32,32,32) f32
// -> (4,64,64,64,32).
//
// Each thread owns one (b, d0, h0, w0, cg) where cg indexes a float4 group of
// the C=32 channel dim. It loads the 8 corners in[d0..d0+1][h0..h0+1][w0..w0+1]
// (clamped at 31) and writes the 2x2x2 output block at (2d0, 2h0, 2w0).
// Even output index -> corner copy; odd -> mean of 2/4/8 corners (frac = 0.5).

__device__ __forceinline__ float4 f4add(float4 a, float4 b) {
    return make_float4(a.x + b.x, a.y + b.y, a.z + b.z, a.w + b.w);
}
__device__ __forceinline__ float4 f4scale(float4 a, float s) {
    return make_float4(a.x * s, a.y * s, a.z * s, a.w * s);
}

__global__ __launch_bounds__(256, 8)
void resize3d_up2_kernel(const float4* __restrict__ in, float4* __restrict__ out) {
    unsigned t = blockIdx.x * 256u + threadIdx.x;
    // total threads = 4 * 32 * 32 * 32 * 8 = 1,048,576
    const int cg = t & 7;          // float4 group within C=32 (8 groups)
    const int w0 = (t >> 3) & 31;
    const int h0 = (t >> 8) & 31;
    const int d0 = (t >> 13) & 31;
    const int b  = t >> 18;

    const int d1 = min(d0 + 1, 31);
    const int h1 = min(h0 + 1, 31);
    const int w1 = min(w0 + 1, 31);

    // input float4 strides: cg=1, w=8, h=256, d=8192, b=262144
    const float4* __restrict__ ib = in + ((size_t)b << 18) + cg;
    const size_t od0 = (size_t)d0 << 13, od1 = (size_t)d1 << 13;
    const size_t oh0 = (size_t)h0 << 8,  oh1 = (size_t)h1 << 8;
    const size_t ow0 = (size_t)w0 << 3,  ow1 = (size_t)w1 << 3;

    const float4 c000 = ib[od0 + oh0 + ow0];
    const float4 c001 = ib[od0 + oh0 + ow1];
    const float4 c010 = ib[od0 + oh1 + ow0];
    const float4 c011 = ib[od0 + oh1 + ow1];
    const float4 c100 = ib[od1 + oh0 + ow0];
    const float4 c101 = ib[od1 + oh0 + ow1];
    const float4 c110 = ib[od1 + oh1 + ow0];
    const float4 c111 = ib[od1 + oh1 + ow1];

    // output float4 strides: cg=1, w=8, h=512, d=32768, b=2097152
    const size_t D = (size_t)(d0 << 1), H = (size_t)(h0 << 1), W = (size_t)(w0 << 1);
    float4* __restrict__ ob =
        out + ((((size_t)b * 64 + D) * 64 + H) * 64 + W) * 8 + cg;

    // partial sums shared across outputs
    const float4 s_w00 = f4add(c000, c001);            // d0,h0 edge along w
    const float4 s_h00 = f4add(c000, c010);            // d0,w0 edge along h
    const float4 s_d00 = f4add(c000, c100);            // h0,w0 edge along d
    const float4 s_hw0 = f4add(s_w00, f4add(c010, c011));   // d0 face (4)
    const float4 s_dw0 = f4add(s_w00, f4add(c100, c101));   // h0 face (4)
    const float4 s_dh0 = f4add(s_h00, f4add(c100, c110));   // w0 face (4)
    const float4 s_all = f4add(s_hw0, f4add(f4add(c100, c101), f4add(c110, c111))); // 8

    ob[0]                 = c000;                      // (0,0,0)
    ob[8]                 = f4scale(s_w00, 0.5f);      // (0,0,1)
    ob[512]               = f4scale(s_h00, 0.5f);      // (0,1,0)
    ob[512 + 8]           = f4scale(s_hw0, 0.25f);     // (0,1,1)
    ob[32768]             = f4scale(s_d00, 0.5f);      // (1,0,0)
    ob[32768 + 8]         = f4scale(s_dw0, 0.25f);     // (1,0,1)
    ob[32768 + 512]       = f4scale(s_dh0, 0.25f);     // (1,1,0)
    ob[32768 + 512 + 8]   = f4scale(s_all, 0.125f);    // (1,1,1)
}

extern "C" void kernel_launch(void* const* d_in, const int* in_sizes, int n_in,
                              void* d_out, int out_size) {
    (void)in_sizes; (void)n_in; (void)out_size;
    const float4* in = (const float4*)d_in[0];
    float4* out = (float4*)d_out;
    // 1,048,576 threads total
    resize3d_up2_kernel<<<4096, 256>>>(in, out);
}

// round 2
// speedup vs baseline: 1.0619x; 1.0619x over previous
#include <cuda_runtime.h>
#include <cstdint>

// 2x trilinear upsample (TF1 legacy, scale=0.5): (4,32,32,32,32) f32 -> (4,64,64,64,32).
//
// Block = (b, d0, h0). Threads (w0 0..31, cg 0..7) load 8 corner float4s,
// compute the 2x2x2 averaged outputs, stage 4 output rows (32 KB) in smem,
// then TMA-bulk-store two contiguous 16 KB spans to global:
//   span0 = rows (D=2d0,   H=2h0) + (D=2d0,   H=2h0+1)
//   span1 = rows (D=2d0+1, H=2h0) + (D=2d0+1, H=2h0+1)

__device__ __forceinline__ float4 f4add(float4 a, float4 b) {
    return make_float4(a.x + b.x, a.y + b.y, a.z + b.z, a.w + b.w);
}
__device__ __forceinline__ float4 f4scale(float4 a, float s) {
    return make_float4(a.x * s, a.y * s, a.z * s, a.w * s);
}

__device__ __forceinline__ uint32_t smem_u32(const void* p) {
    uint32_t a;
    asm("{ .reg .u64 t; cvta.to.shared.u64 t, %1; cvt.u32.u64 %0, t; }"
        : "=r"(a) : "l"(p));
    return a;
}

__global__ __launch_bounds__(256)
void resize3d_up2_tma_kernel(const float4* __restrict__ in, float4* __restrict__ out) {
    // 4 output rows of 8 KB each: [rowA | rowB | rowC | rowD]
    __shared__ __align__(128) float4 sbuf[2048];   // 32 KB

    const int tid = threadIdx.x;
    const int cg  = tid & 7;        // float4 group within C=32
    const int w0  = tid >> 3;       // 0..31

    const int blk = blockIdx.x;     // 4096 blocks
    const int h0  = blk & 31;
    const int d0  = (blk >> 5) & 31;
    const int b   = blk >> 10;

    const int w1 = min(w0 + 1, 31);
    const int h1 = min(h0 + 1, 31);
    const int d1 = min(d0 + 1, 31);

    // input float4 strides: cg=1, w=8, h=256, d=8192, b=262144
    const float4* __restrict__ ib = in + ((size_t)b << 18) + (size_t)cg;
    const size_t od0 = (size_t)d0 << 13, od1 = (size_t)d1 << 13;
    const size_t oh0 = (size_t)h0 << 8,  oh1 = (size_t)h1 << 8;
    const size_t ow0 = (size_t)w0 << 3,  ow1 = (size_t)w1 << 3;

    const float4 r00a = ib[od0 + oh0 + ow0];
    const float4 r00b = ib[od0 + oh0 + ow1];
    const float4 r01a = ib[od0 + oh1 + ow0];
    const float4 r01b = ib[od0 + oh1 + ow1];
    const float4 r10a = ib[od1 + oh0 + ow0];
    const float4 r10b = ib[od1 + oh0 + ow1];
    const float4 r11a = ib[od1 + oh1 + ow0];
    const float4 r11b = ib[od1 + oh1 + ow1];

    // shared partial sums
    const float4 sA = f4add(r00a, r00b);                  // w-pair, (d0,h0)
    const float4 sB0 = f4add(r00a, r01a);                 // h-pair even w
    const float4 sB1 = f4add(sA, f4add(r01a, r01b));      // h-quad odd w
    const float4 sC0 = f4add(r00a, r10a);                 // d-pair even w
    const float4 sC1 = f4add(sA, f4add(r10a, r10b));      // d-quad odd w
    const float4 sD0 = f4add(sB0, f4add(r10a, r11a));     // dh-quad even w
    const float4 sD1 = f4add(sB1, f4add(f4add(r10a, r10b), f4add(r11a, r11b))); // all 8

    // smem row layout: W*8 + cg within a 512-float4 row
    const int we = (w0 << 4) + cg;        // (2*w0)*8 + cg
    sbuf[we]            = r00a;                      // rowA even
    sbuf[we + 8]        = f4scale(sA,  0.5f);        // rowA odd
    sbuf[512 + we]      = f4scale(sB0, 0.5f);        // rowB even
    sbuf[512 + we + 8]  = f4scale(sB1, 0.25f);       // rowB odd
    sbuf[1024 + we]     = f4scale(sC0, 0.5f);        // rowC even
    sbuf[1024 + we + 8] = f4scale(sC1, 0.25f);       // rowC odd
    sbuf[1536 + we]     = f4scale(sD0, 0.25f);       // rowD even
    sbuf[1536 + we + 8] = f4scale(sD1, 0.125f);      // rowD odd

    // make generic-proxy smem writes visible to the async (TMA) proxy
    asm volatile("fence.proxy.async.shared::cta;" ::: "memory");
    __syncthreads();

    if (tid == 0) {
        const uint32_t s0 = smem_u32(sbuf);
        // output row offset: ((b*64 + D)*64 + H) * 8192 bytes
        char* g0 = (char*)out + (size_t)(((b * 64 + 2 * d0) * 64) + 2 * h0) * 8192;
        char* g1 = g0 + (size_t)64 * 8192;   // D+1
        const uint32_t half = 16384u;
        asm volatile("cp.async.bulk.global.shared::cta.bulk_group [%0], [%1], %2;"
                     :: "l"(g0), "r"(s0), "r"(half) : "memory");
        asm volatile("cp.async.bulk.global.shared::cta.bulk_group [%0], [%1], %2;"
                     :: "l"(g1), "r"(s0 + half), "r"(half) : "memory");
        asm volatile("cp.async.bulk.commit_group;" ::: "memory");
        asm volatile("cp.async.bulk.wait_group 0;" ::: "memory");
    }
}

extern "C" void kernel_launch(void* const* d_in, const int* in_sizes, int n_in,
                              void* d_out, int out_size) {
    (void)in_sizes; (void)n_in; (void)out_size;
    const float4* in = (const float4*)d_in[0];
    float4* out = (float4*)d_out;
    resize3d_up2_tma_kernel<<<4096, 256>>>(in, out);
}